// round 1
// baseline (speedup 1.0000x reference)
#include <cuda_runtime.h>
#include <cuda_bf16.h>
#include <math.h>

// Problem constants
#define BATCH 4
#define SEQ 2048
#define DMODEL 1024
#define NHEADS 16
#define HDIM 64
#define MTOT (BATCH * SEQ)          // 8192 rows

// ---------------------------------------------------------------------------
// Scratch (device globals: allocation-free, graph-safe)
// ---------------------------------------------------------------------------
__device__ float g_q[MTOT * DMODEL];
__device__ float g_k[MTOT * DMODEL];
__device__ float g_v[MTOT * DMODEL];
__device__ float g_attn[MTOT * DMODEL];

// ---------------------------------------------------------------------------
// Tiled GEMM: C[M,N] = A[M,K] @ B[K,N] (+ bias). 64x64 tile, BK=16,
// 256 threads, 4x4 register micro-tile per thread.
// ---------------------------------------------------------------------------
__global__ __launch_bounds__(256)
void gemm64_kernel(const float* __restrict__ A, const float* __restrict__ B,
                   const float* __restrict__ bias, float* __restrict__ C,
                   int M, int N, int K, int useBias)
{
    __shared__ float As[16][68];   // As[k][m] (A transposed in smem)
    __shared__ float Bs[16][68];   // Bs[k][n]

    const int tid = threadIdx.x;
    const int tx = tid & 15;
    const int ty = tid >> 4;
    const int m0 = blockIdx.y * 64;
    const int n0 = blockIdx.x * 64;

    // A-load mapping: one float4 per thread per k-tile
    const int am = tid >> 2;              // 0..63
    const int ak = (tid & 3) << 2;        // 0,4,8,12
    // B-load mapping
    const int bk = tid >> 4;              // 0..15
    const int bn = (tid & 15) << 2;       // 0..60

    const float* Aptr = A + (size_t)(m0 + am) * K + ak;
    const float* Bptr = B + (size_t)bk * N + n0 + bn;

    float acc[4][4] = {};

    for (int k0 = 0; k0 < K; k0 += 16) {
        float4 a = *(const float4*)(Aptr + k0);
        float4 b = *(const float4*)(Bptr + (size_t)k0 * N);
        As[ak + 0][am] = a.x;
        As[ak + 1][am] = a.y;
        As[ak + 2][am] = a.z;
        As[ak + 3][am] = a.w;
        *(float4*)&Bs[bk][bn] = b;
        __syncthreads();

#pragma unroll
        for (int kk = 0; kk < 16; kk++) {
            float4 av = *(const float4*)&As[kk][ty * 4];
            float4 bv = *(const float4*)&Bs[kk][tx * 4];
            float ar[4] = {av.x, av.y, av.z, av.w};
            float br[4] = {bv.x, bv.y, bv.z, bv.w};
#pragma unroll
            for (int i = 0; i < 4; i++)
#pragma unroll
                for (int j = 0; j < 4; j++)
                    acc[i][j] = fmaf(ar[i], br[j], acc[i][j]);
        }
        __syncthreads();
    }

    float4 bvec = {0.f, 0.f, 0.f, 0.f};
    if (useBias) bvec = *(const float4*)(bias + n0 + tx * 4);

#pragma unroll
    for (int i = 0; i < 4; i++) {
        int row = m0 + ty * 4 + i;
        float4 out;
        out.x = acc[i][0] + bvec.x;
        out.y = acc[i][1] + bvec.y;
        out.z = acc[i][2] + bvec.z;
        out.w = acc[i][3] + bvec.w;
        *(float4*)(C + (size_t)row * N + n0 + tx * 4) = out;
    }
}

// ---------------------------------------------------------------------------
// Flash attention (causal). One CTA = one (b,h) and one 64-row Q tile.
// Layouts are [B, S, D] with head slice at column h*64.
// ---------------------------------------------------------------------------
struct AttnSmem {
    float Qs[64][68];     // Qs[d][r]   (Q transposed)
    float Ks[64][68];     // Ks[d][c]   (K transposed)
    float Vs[64][68];     // Vs[c][d]   (natural)
    float Ps[64][68];     // Ps[c][r]   (S^T, then exp(P)^T)
    float row_scale[64];
    float row_inv[64];
};

__global__ __launch_bounds__(256)
void attn_kernel(const float* __restrict__ q, const float* __restrict__ k,
                 const float* __restrict__ v, float* __restrict__ out)
{
    extern __shared__ char smem_raw[];
    AttnSmem& sm = *reinterpret_cast<AttnSmem*>(smem_raw);

    const int tid = threadIdx.x;
    const int tx = tid & 15;
    const int ty = tid >> 4;
    const int q0 = blockIdx.x * 64;
    const int bh = blockIdx.y;
    const int b = bh >> 4;
    const int h = bh & 15;
    const float scale = 0.125f;   // 1/sqrt(64)

    const size_t base = (size_t)b * SEQ * DMODEL + (size_t)h * HDIM;

    // Load Q tile transposed: Qs[d][r]
    for (int idx = tid; idx < 1024; idx += 256) {   // 1024 float4s
        int r = idx >> 4;
        int d4 = (idx & 15) << 2;
        float4 val = *(const float4*)(q + base + (size_t)(q0 + r) * DMODEL + d4);
        sm.Qs[d4 + 0][r] = val.x;
        sm.Qs[d4 + 1][r] = val.y;
        sm.Qs[d4 + 2][r] = val.z;
        sm.Qs[d4 + 3][r] = val.w;
    }

    float m_i = -INFINITY;
    float l_i = 0.f;
    const int row = tid;          // softmax ownership for tid < 64
    float o[4][4] = {};

    for (int k0 = 0; k0 <= q0; k0 += 64) {
        __syncthreads();   // previous iteration done reading Ks/Vs/Ps (also covers Q load 1st iter)

        // Load K tile transposed and V tile natural
        for (int idx = tid; idx < 1024; idx += 256) {
            int c = idx >> 4;
            int d4 = (idx & 15) << 2;
            float4 kv = *(const float4*)(k + base + (size_t)(k0 + c) * DMODEL + d4);
            sm.Ks[d4 + 0][c] = kv.x;
            sm.Ks[d4 + 1][c] = kv.y;
            sm.Ks[d4 + 2][c] = kv.z;
            sm.Ks[d4 + 3][c] = kv.w;
            float4 vv = *(const float4*)(v + base + (size_t)(k0 + c) * DMODEL + d4);
            *(float4*)&sm.Vs[c][d4] = vv;
        }
        __syncthreads();

        // S = Q @ K^T (tile), 4x4 per thread
        float s[4][4] = {};
#pragma unroll 8
        for (int d = 0; d < 64; d++) {
            float4 qa = *(const float4*)&sm.Qs[d][ty * 4];
            float4 kb = *(const float4*)&sm.Ks[d][tx * 4];
            float qr[4] = {qa.x, qa.y, qa.z, qa.w};
            float kr[4] = {kb.x, kb.y, kb.z, kb.w};
#pragma unroll
            for (int i = 0; i < 4; i++)
#pragma unroll
                for (int j = 0; j < 4; j++)
                    s[i][j] = fmaf(qr[i], kr[j], s[i][j]);
        }
        // Write S^T into Ps: Ps[col][row]
#pragma unroll
        for (int i = 0; i < 4; i++)
#pragma unroll
            for (int j = 0; j < 4; j++)
                sm.Ps[tx * 4 + j][ty * 4 + i] = s[i][j];
        __syncthreads();

        // Online softmax: one thread per row (tid < 64)
        if (tid < 64) {
            const int climit = q0 + row - k0;   // keep columns c <= climit
            float mtile = -INFINITY;
            for (int c = 0; c < 64; c++) {
                float sv = sm.Ps[c][row] * scale;
                if (c <= climit) mtile = fmaxf(mtile, sv);
            }
            float mnew = fmaxf(m_i, mtile);
            float rs = __expf(m_i - mnew);      // exp(-inf)=0 on first tile
            float lsum = 0.f;
            for (int c = 0; c < 64; c++) {
                float sv = sm.Ps[c][row] * scale;
                float p = (c <= climit) ? __expf(sv - mnew) : 0.f;
                sm.Ps[c][row] = p;
                lsum += p;
            }
            l_i = l_i * rs + lsum;
            m_i = mnew;
            sm.row_scale[row] = rs;
        }
        __syncthreads();

        // Rescale accumulator and add P @ V
        float rs[4];
#pragma unroll
        for (int i = 0; i < 4; i++) rs[i] = sm.row_scale[ty * 4 + i];
#pragma unroll
        for (int i = 0; i < 4; i++)
#pragma unroll
            for (int j = 0; j < 4; j++)
                o[i][j] *= rs[i];

#pragma unroll 8
        for (int c = 0; c < 64; c++) {
            float4 pv = *(const float4*)&sm.Ps[c][ty * 4];
            float4 vv = *(const float4*)&sm.Vs[c][tx * 4];
            float pr[4] = {pv.x, pv.y, pv.z, pv.w};
            float vr[4] = {vv.x, vv.y, vv.z, vv.w};
#pragma unroll
            for (int i = 0; i < 4; i++)
#pragma unroll
                for (int j = 0; j < 4; j++)
                    o[i][j] = fmaf(pr[i], vr[j], o[i][j]);
        }
    }

    __syncthreads();
    if (tid < 64) sm.row_inv[row] = 1.f / l_i;
    __syncthreads();

#pragma unroll
    for (int i = 0; i < 4; i++) {
        float inv = sm.row_inv[ty * 4 + i];
        float4 res;
        res.x = o[i][0] * inv;
        res.y = o[i][1] * inv;
        res.z = o[i][2] * inv;
        res.w = o[i][3] * inv;
        *(float4*)(out + base + (size_t)(q0 + ty * 4 + i) * DMODEL + tx * 4) = res;
    }
}

// ---------------------------------------------------------------------------
// Launch
// ---------------------------------------------------------------------------
extern "C" void kernel_launch(void* const* d_in, const int* in_sizes, int n_in,
                              void* d_out, int out_size)
{
    const float* x  = (const float*)d_in[0];
    const float* Wq = (const float*)d_in[1];
    const float* Wk = (const float*)d_in[2];
    const float* Wv = (const float*)d_in[3];
    const float* Wo = (const float*)d_in[4];
    const float* bo = (const float*)d_in[5];
    float* out = (float*)d_out;

    float *qp, *kp, *vp, *ap;
    cudaGetSymbolAddress((void**)&qp, g_q);
    cudaGetSymbolAddress((void**)&kp, g_k);
    cudaGetSymbolAddress((void**)&vp, g_v);
    cudaGetSymbolAddress((void**)&ap, g_attn);

    cudaFuncSetAttribute(attn_kernel, cudaFuncAttributeMaxDynamicSharedMemorySize,
                         (int)sizeof(AttnSmem));

    dim3 gblk(DMODEL / 64, MTOT / 64);   // (16, 128)
    dim3 tblk(256);

    // QKV projections
    gemm64_kernel<<<gblk, tblk>>>(x, Wq, nullptr, qp, MTOT, DMODEL, DMODEL, 0);
    gemm64_kernel<<<gblk, tblk>>>(x, Wk, nullptr, kp, MTOT, DMODEL, DMODEL, 0);
    gemm64_kernel<<<gblk, tblk>>>(x, Wv, nullptr, vp, MTOT, DMODEL, DMODEL, 0);

    // Causal flash attention
    dim3 agrid(SEQ / 64, BATCH * NHEADS);   // (32, 64)
    attn_kernel<<<agrid, tblk, sizeof(AttnSmem)>>>(qp, kp, vp, ap);

    // Output projection + bias
    gemm64_kernel<<<gblk, tblk>>>(ap, Wo, bo, out, MTOT, DMODEL, DMODEL, 1);
}

// round 4
// speedup vs baseline: 1.6589x; 1.6589x over previous
#include <cuda_runtime.h>
#include <cuda_bf16.h>
#include <math.h>
#include <stdint.h>

// Problem constants
#define BATCH 4
#define SEQ 2048
#define DMODEL 1024
#define NHEADS 16
#define HDIM 64
#define MTOT (BATCH * SEQ)          // 8192 rows

// ---------------------------------------------------------------------------
// Scratch (device globals: allocation-free, graph-safe)
// ---------------------------------------------------------------------------
__device__ float g_q[MTOT * DMODEL];
__device__ float g_k[MTOT * DMODEL];
__device__ float g_v[MTOT * DMODEL];
__device__ float g_attn[MTOT * DMODEL];

// ---------------------------------------------------------------------------
// Helpers
// ---------------------------------------------------------------------------
__device__ __forceinline__ uint32_t smem_to_u32(const void* p) {
    uint32_t a;
    asm("{ .reg .u64 t; cvta.to.shared.u64 t, %1; cvt.u32.u64 %0, t; }"
        : "=r"(a) : "l"(p));
    return a;
}
__device__ __forceinline__ void cp_async16(uint32_t dst, const void* src) {
    asm volatile("cp.async.cg.shared.global [%0], [%1], 16;" :: "r"(dst), "l"(src));
}
#define CP_COMMIT() asm volatile("cp.async.commit_group;" ::: "memory")
#define CP_WAIT2()  asm volatile("cp.async.wait_group 2;" ::: "memory")

__device__ __forceinline__ uint32_t f2tf32(float f) {
    uint32_t r;
    asm("cvt.rna.tf32.f32 %0, %1;" : "=r"(r) : "f"(f));
    return r;
}
__device__ __forceinline__ void mma_tf32(float* c, const uint32_t* a, const uint32_t* b) {
    asm volatile(
        "mma.sync.aligned.m16n8k8.row.col.f32.tf32.tf32.f32 "
        "{%0,%1,%2,%3}, {%4,%5,%6,%7}, {%8,%9}, {%0,%1,%2,%3};"
        : "+f"(c[0]), "+f"(c[1]), "+f"(c[2]), "+f"(c[3])
        : "r"(a[0]), "r"(a[1]), "r"(a[2]), "r"(a[3]), "r"(b[0]), "r"(b[1]));
}

// ---------------------------------------------------------------------------
// tf32 mma.sync GEMM: C[M,N] = A[M,K] @ B[K,N] (+bias)
// BM=128 BN=128 BK=16, 256 threads (8 warps, 4 along M x 2 along N),
// warp tile 32x64 = 2x8 m16n8k8 MMAs per k8 step. 3-stage cp.async pipeline.
//   As[m][k]: 128 rows x 16 floats, pad to 20  (conflict-free frag reads)
//   Bs[k][n]: 16 rows x 128 floats, pad to 136
// ---------------------------------------------------------------------------
#define GKDIM 1024
#define GNDIM 1024
#define NKT 64                          // 1024/16
#define A_STRIDE 20
#define B_STRIDE 136
#define A_BYTES (128 * A_STRIDE * 4)    // 10240
#define B_BYTES (16 * B_STRIDE * 4)     // 8704
#define STAGE_BYTES (A_BYTES + B_BYTES) // 18944
#define GSTAGES 3
#define GEMM_SMEM (GSTAGES * STAGE_BYTES)

__global__ __launch_bounds__(256)
void gemm_tc_kernel(const float* __restrict__ A, const float* __restrict__ B,
                    const float* __restrict__ bias, float* __restrict__ C,
                    int useBias)
{
    extern __shared__ char dsmem[];
    const int tid = threadIdx.x;
    const int wid = tid >> 5;
    const int lane = tid & 31;
    const int n0 = blockIdx.x * 128;
    const int m0 = blockIdx.y * 128;
    const int wm0 = (wid & 3) * 32;     // warp M offset
    const int wn0 = (wid >> 2) * 64;    // warp N offset
    const int qr = lane >> 2;           // 0..7
    const int qc = lane & 3;            // 0..3

    const uint32_t sbase = smem_to_u32(dsmem);

    float acc[2][8][4];
#pragma unroll
    for (int i = 0; i < 2; i++)
#pragma unroll
        for (int j = 0; j < 8; j++)
#pragma unroll
            for (int l = 0; l < 4; l++) acc[i][j][l] = 0.f;

    // ---- stage loader: 4 cp.async16 per thread ----
    auto issue_stage = [&](int stage, int k0) {
        uint32_t aB = sbase + stage * STAGE_BYTES;
        uint32_t bB = aB + A_BYTES;
#pragma unroll
        for (int i = 0; i < 2; i++) {
            int idx = tid * 2 + i;              // 0..511
            int row = idx >> 2;                 // 0..127
            int c4 = idx & 3;                   // 0..3
            cp_async16(aB + row * (A_STRIDE * 4) + c4 * 16,
                       A + (size_t)(m0 + row) * GKDIM + k0 + c4 * 4);
            int krow = idx >> 5;                // 0..15
            int col = idx & 31;                 // 0..31
            cp_async16(bB + krow * (B_STRIDE * 4) + col * 16,
                       B + (size_t)(k0 + krow) * GNDIM + n0 + col * 4);
        }
    };

    // prologue: stages 0,1
    issue_stage(0, 0);
    CP_COMMIT();
    issue_stage(1, 16);
    CP_COMMIT();

    for (int kt = 0; kt < NKT; kt++) {
        int lt = kt + 2;
        if (lt < NKT) issue_stage(lt % GSTAGES, lt * 16);
        CP_COMMIT();
        CP_WAIT2();
        __syncthreads();

        const float* As = (const float*)(dsmem + (kt % GSTAGES) * STAGE_BYTES);
        const float* Bs = (const float*)(dsmem + (kt % GSTAGES) * STAGE_BYTES + A_BYTES);

#pragma unroll
        for (int ks = 0; ks < 2; ks++) {
            const int kb = ks * 8;
            uint32_t afr[2][4];
            uint32_t bfr[8][2];
#pragma unroll
            for (int mt = 0; mt < 2; mt++) {
                int mbase = wm0 + mt * 16;
                afr[mt][0] = f2tf32(As[(mbase + qr) * A_STRIDE + kb + qc]);
                afr[mt][1] = f2tf32(As[(mbase + qr + 8) * A_STRIDE + kb + qc]);
                afr[mt][2] = f2tf32(As[(mbase + qr) * A_STRIDE + kb + qc + 4]);
                afr[mt][3] = f2tf32(As[(mbase + qr + 8) * A_STRIDE + kb + qc + 4]);
            }
#pragma unroll
            for (int nt = 0; nt < 8; nt++) {
                int nc = wn0 + nt * 8 + qr;
                bfr[nt][0] = f2tf32(Bs[(kb + qc) * B_STRIDE + nc]);
                bfr[nt][1] = f2tf32(Bs[(kb + qc + 4) * B_STRIDE + nc]);
            }
#pragma unroll
            for (int mt = 0; mt < 2; mt++)
#pragma unroll
                for (int nt = 0; nt < 8; nt++)
                    mma_tf32(acc[mt][nt], afr[mt], bfr[nt]);
        }
        __syncthreads();
    }

    // ---- epilogue: direct float2 stores ----
#pragma unroll
    for (int mt = 0; mt < 2; mt++) {
        int r0 = m0 + wm0 + mt * 16 + qr;
#pragma unroll
        for (int nt = 0; nt < 8; nt++) {
            int col = n0 + wn0 + nt * 8 + 2 * qc;
            float bx = 0.f, by = 0.f;
            if (useBias) {
                float2 bb = *(const float2*)(bias + col);
                bx = bb.x; by = bb.y;
            }
            float2 v0 = {acc[mt][nt][0] + bx, acc[mt][nt][1] + by};
            float2 v1 = {acc[mt][nt][2] + bx, acc[mt][nt][3] + by};
            *(float2*)(C + (size_t)r0 * GNDIM + col) = v0;
            *(float2*)(C + (size_t)(r0 + 8) * GNDIM + col) = v1;
        }
    }
}

// ---------------------------------------------------------------------------
// Flash attention (causal), fp32 SIMT with parallel softmax.
// One CTA = (b,h) x 64-row Q tile, 256 threads.
// ---------------------------------------------------------------------------
struct AttnSmem {
    float Qs[64][68];
    float Ks[64][68];
    float Vs[64][68];
    float Ps[64][68];
    float red_max[4][64];
    float red_sum[4][64];
    float row_mnew[64];
    float row_scale[64];
    float row_inv[64];
};

__global__ __launch_bounds__(256)
void attn_kernel(const float* __restrict__ q, const float* __restrict__ k,
                 const float* __restrict__ v, float* __restrict__ out)
{
    extern __shared__ char smem_raw[];
    AttnSmem& sm = *reinterpret_cast<AttnSmem*>(smem_raw);

    const int tid = threadIdx.x;
    const int tx = tid & 15;
    const int ty = tid >> 4;
    const int q0 = blockIdx.x * 64;
    const int bh = blockIdx.y;
    const int b = bh >> 4;
    const int h = bh & 15;
    const float scale = 0.125f;

    const size_t base = (size_t)b * SEQ * DMODEL + (size_t)h * HDIM;

    for (int idx = tid; idx < 1024; idx += 256) {
        int r = idx >> 4;
        int d4 = (idx & 15) << 2;
        float4 val = *(const float4*)(q + base + (size_t)(q0 + r) * DMODEL + d4);
        sm.Qs[d4 + 0][r] = val.x;
        sm.Qs[d4 + 1][r] = val.y;
        sm.Qs[d4 + 2][r] = val.z;
        sm.Qs[d4 + 3][r] = val.w;
    }

    float m_i = -INFINITY;
    float l_i = 0.f;
    const int rr = tid & 63;
    const int qx = tid >> 6;
    float o[4][4] = {};

    for (int k0 = 0; k0 <= q0; k0 += 64) {
        __syncthreads();

        for (int idx = tid; idx < 1024; idx += 256) {
            int c = idx >> 4;
            int d4 = (idx & 15) << 2;
            float4 kv = *(const float4*)(k + base + (size_t)(k0 + c) * DMODEL + d4);
            sm.Ks[d4 + 0][c] = kv.x;
            sm.Ks[d4 + 1][c] = kv.y;
            sm.Ks[d4 + 2][c] = kv.z;
            sm.Ks[d4 + 3][c] = kv.w;
            float4 vv = *(const float4*)(v + base + (size_t)(k0 + c) * DMODEL + d4);
            *(float4*)&sm.Vs[c][d4] = vv;
        }
        __syncthreads();

        // S = Q @ K^T
        float s[4][4] = {};
#pragma unroll 8
        for (int d = 0; d < 64; d++) {
            float4 qa = *(const float4*)&sm.Qs[d][ty * 4];
            float4 kb = *(const float4*)&sm.Ks[d][tx * 4];
            float qr4[4] = {qa.x, qa.y, qa.z, qa.w};
            float kr[4] = {kb.x, kb.y, kb.z, kb.w};
#pragma unroll
            for (int i = 0; i < 4; i++)
#pragma unroll
                for (int j = 0; j < 4; j++)
                    s[i][j] = fmaf(qr4[i], kr[j], s[i][j]);
        }
#pragma unroll
        for (int i = 0; i < 4; i++)
#pragma unroll
            for (int j = 0; j < 4; j++)
                sm.Ps[tx * 4 + j][ty * 4 + i] = s[i][j];
        __syncthreads();

        // Online softmax: 4 threads per row, 16 cols each
        const int climit = q0 + rr - k0;
        const int c0 = qx * 16;
        float mtile = -INFINITY;
#pragma unroll
        for (int c = c0; c < c0 + 16; c++) {
            if (c <= climit) mtile = fmaxf(mtile, sm.Ps[c][rr] * scale);
        }
        sm.red_max[qx][rr] = mtile;
        __syncthreads();
        if (tid < 64) {
            float mt = fmaxf(fmaxf(sm.red_max[0][rr], sm.red_max[1][rr]),
                             fmaxf(sm.red_max[2][rr], sm.red_max[3][rr]));
            float mnew = fmaxf(m_i, mt);
            sm.row_mnew[rr] = mnew;
            sm.row_scale[rr] = __expf(m_i - mnew);
        }
        __syncthreads();
        {
            float mnew = sm.row_mnew[rr];
            float lsum = 0.f;
#pragma unroll
            for (int c = c0; c < c0 + 16; c++) {
                float sv = sm.Ps[c][rr] * scale;
                float p = (c <= climit) ? __expf(sv - mnew) : 0.f;
                sm.Ps[c][rr] = p;
                lsum += p;
            }
            sm.red_sum[qx][rr] = lsum;
        }
        __syncthreads();
        if (tid < 64) {
            l_i = l_i * sm.row_scale[rr] +
                  sm.red_sum[0][rr] + sm.red_sum[1][rr] + sm.red_sum[2][rr] + sm.red_sum[3][rr];
            m_i = sm.row_mnew[rr];
        }

        // Rescale accumulator and add P @ V
        float rs[4];
#pragma unroll
        for (int i = 0; i < 4; i++) rs[i] = sm.row_scale[ty * 4 + i];
#pragma unroll
        for (int i = 0; i < 4; i++)
#pragma unroll
            for (int j = 0; j < 4; j++)
                o[i][j] *= rs[i];

#pragma unroll 8
        for (int c = 0; c < 64; c++) {
            float4 pv = *(const float4*)&sm.Ps[c][ty * 4];
            float4 vv = *(const float4*)&sm.Vs[c][tx * 4];
            float pr[4] = {pv.x, pv.y, pv.z, pv.w};
            float vr[4] = {vv.x, vv.y, vv.z, vv.w};
#pragma unroll
            for (int i = 0; i < 4; i++)
#pragma unroll
                for (int j = 0; j < 4; j++)
                    o[i][j] = fmaf(pr[i], vr[j], o[i][j]);
        }
    }

    __syncthreads();
    if (tid < 64) sm.row_inv[rr] = 1.f / l_i;
    __syncthreads();

#pragma unroll
    for (int i = 0; i < 4; i++) {
        float inv = sm.row_inv[ty * 4 + i];
        float4 res;
        res.x = o[i][0] * inv;
        res.y = o[i][1] * inv;
        res.z = o[i][2] * inv;
        res.w = o[i][3] * inv;
        *(float4*)(out + base + (size_t)(q0 + ty * 4 + i) * DMODEL + tx * 4) = res;
    }
}

// ---------------------------------------------------------------------------
// Launch
// ---------------------------------------------------------------------------
extern "C" void kernel_launch(void* const* d_in, const int* in_sizes, int n_in,
                              void* d_out, int out_size)
{
    const float* x  = (const float*)d_in[0];
    const float* Wq = (const float*)d_in[1];
    const float* Wk = (const float*)d_in[2];
    const float* Wv = (const float*)d_in[3];
    const float* Wo = (const float*)d_in[4];
    const float* bo = (const float*)d_in[5];
    float* out = (float*)d_out;

    float *qp, *kp, *vp, *ap;
    cudaGetSymbolAddress((void**)&qp, g_q);
    cudaGetSymbolAddress((void**)&kp, g_k);
    cudaGetSymbolAddress((void**)&vp, g_v);
    cudaGetSymbolAddress((void**)&ap, g_attn);

    cudaFuncSetAttribute(gemm_tc_kernel, cudaFuncAttributeMaxDynamicSharedMemorySize, GEMM_SMEM);
    cudaFuncSetAttribute(attn_kernel, cudaFuncAttributeMaxDynamicSharedMemorySize,
                         (int)sizeof(AttnSmem));

    dim3 ggrid(GNDIM / 128, MTOT / 128);   // (8, 64)

    gemm_tc_kernel<<<ggrid, 256, GEMM_SMEM>>>(x, Wq, nullptr, qp, 0);
    gemm_tc_kernel<<<ggrid, 256, GEMM_SMEM>>>(x, Wk, nullptr, kp, 0);
    gemm_tc_kernel<<<ggrid, 256, GEMM_SMEM>>>(x, Wv, nullptr, vp, 0);

    dim3 agrid(SEQ / 64, BATCH * NHEADS);
    attn_kernel<<<agrid, 256, sizeof(AttnSmem)>>>(qp, kp, vp, ap);

    gemm_tc_kernel<<<ggrid, 256, GEMM_SMEM>>>(ap, Wo, bo, out, 1);
}

// round 5
// speedup vs baseline: 2.6021x; 1.5685x over previous
#include <cuda_runtime.h>
#include <cuda_bf16.h>
#include <math.h>
#include <stdint.h>

// Problem constants
#define BATCH 4
#define SEQ 2048
#define DMODEL 1024
#define NHEADS 16
#define HDIM 64
#define MTOT (BATCH * SEQ)          // 8192 rows

// ---------------------------------------------------------------------------
// Scratch (device globals: allocation-free, graph-safe)
// ---------------------------------------------------------------------------
__device__ float g_q[MTOT * DMODEL];
__device__ float g_k[MTOT * DMODEL];
__device__ float g_v[MTOT * DMODEL];
__device__ float g_attn[MTOT * DMODEL];

// ---------------------------------------------------------------------------
// Helpers
// ---------------------------------------------------------------------------
__device__ __forceinline__ uint32_t smem_to_u32(const void* p) {
    uint32_t a;
    asm("{ .reg .u64 t; cvta.to.shared.u64 t, %1; cvt.u32.u64 %0, t; }"
        : "=r"(a) : "l"(p));
    return a;
}
__device__ __forceinline__ void cp_async16(uint32_t dst, const void* src) {
    asm volatile("cp.async.cg.shared.global [%0], [%1], 16;" :: "r"(dst), "l"(src));
}
#define CP_COMMIT() asm volatile("cp.async.commit_group;" ::: "memory")
#define CP_WAIT0()  asm volatile("cp.async.wait_group 0;" ::: "memory")
#define CP_WAIT2()  asm volatile("cp.async.wait_group 2;" ::: "memory")

__device__ __forceinline__ uint32_t f2tf32(float f) {
    uint32_t r;
    asm("cvt.rna.tf32.f32 %0, %1;" : "=r"(r) : "f"(f));
    return r;
}
__device__ __forceinline__ void mma_tf32(float* c, const uint32_t* a, const uint32_t* b) {
    asm volatile(
        "mma.sync.aligned.m16n8k8.row.col.f32.tf32.tf32.f32 "
        "{%0,%1,%2,%3}, {%4,%5,%6,%7}, {%8,%9}, {%0,%1,%2,%3};"
        : "+f"(c[0]), "+f"(c[1]), "+f"(c[2]), "+f"(c[3])
        : "r"(a[0]), "r"(a[1]), "r"(a[2]), "r"(a[3]), "r"(b[0]), "r"(b[1]));
}

// ---------------------------------------------------------------------------
// tf32 mma.sync GEMM: C[M,N] = A[M,K] @ B[K,N] (+bias)   (unchanged from R4)
// ---------------------------------------------------------------------------
#define GKDIM 1024
#define GNDIM 1024
#define NKT 64
#define A_STRIDE 20
#define B_STRIDE 136
#define A_BYTES (128 * A_STRIDE * 4)
#define B_BYTES (16 * B_STRIDE * 4)
#define STAGE_BYTES (A_BYTES + B_BYTES)
#define GSTAGES 3
#define GEMM_SMEM (GSTAGES * STAGE_BYTES)

__global__ __launch_bounds__(256)
void gemm_tc_kernel(const float* __restrict__ A, const float* __restrict__ B,
                    const float* __restrict__ bias, float* __restrict__ C,
                    int useBias)
{
    extern __shared__ char dsmem[];
    const int tid = threadIdx.x;
    const int wid = tid >> 5;
    const int lane = tid & 31;
    const int n0 = blockIdx.x * 128;
    const int m0 = blockIdx.y * 128;
    const int wm0 = (wid & 3) * 32;
    const int wn0 = (wid >> 2) * 64;
    const int qr = lane >> 2;
    const int qc = lane & 3;

    const uint32_t sbase = smem_to_u32(dsmem);

    float acc[2][8][4];
#pragma unroll
    for (int i = 0; i < 2; i++)
#pragma unroll
        for (int j = 0; j < 8; j++)
#pragma unroll
            for (int l = 0; l < 4; l++) acc[i][j][l] = 0.f;

    auto issue_stage = [&](int stage, int k0) {
        uint32_t aB = sbase + stage * STAGE_BYTES;
        uint32_t bB = aB + A_BYTES;
#pragma unroll
        for (int i = 0; i < 2; i++) {
            int idx = tid * 2 + i;
            int row = idx >> 2;
            int c4 = idx & 3;
            cp_async16(aB + row * (A_STRIDE * 4) + c4 * 16,
                       A + (size_t)(m0 + row) * GKDIM + k0 + c4 * 4);
            int krow = idx >> 5;
            int col = idx & 31;
            cp_async16(bB + krow * (B_STRIDE * 4) + col * 16,
                       B + (size_t)(k0 + krow) * GNDIM + n0 + col * 4);
        }
    };

    issue_stage(0, 0);
    CP_COMMIT();
    issue_stage(1, 16);
    CP_COMMIT();

    for (int kt = 0; kt < NKT; kt++) {
        int lt = kt + 2;
        if (lt < NKT) issue_stage(lt % GSTAGES, lt * 16);
        CP_COMMIT();
        CP_WAIT2();
        __syncthreads();

        const float* As = (const float*)(dsmem + (kt % GSTAGES) * STAGE_BYTES);
        const float* Bs = (const float*)(dsmem + (kt % GSTAGES) * STAGE_BYTES + A_BYTES);

#pragma unroll
        for (int ks = 0; ks < 2; ks++) {
            const int kb = ks * 8;
            uint32_t afr[2][4];
            uint32_t bfr[8][2];
#pragma unroll
            for (int mt = 0; mt < 2; mt++) {
                int mbase = wm0 + mt * 16;
                afr[mt][0] = f2tf32(As[(mbase + qr) * A_STRIDE + kb + qc]);
                afr[mt][1] = f2tf32(As[(mbase + qr + 8) * A_STRIDE + kb + qc]);
                afr[mt][2] = f2tf32(As[(mbase + qr) * A_STRIDE + kb + qc + 4]);
                afr[mt][3] = f2tf32(As[(mbase + qr + 8) * A_STRIDE + kb + qc + 4]);
            }
#pragma unroll
            for (int nt = 0; nt < 8; nt++) {
                int nc = wn0 + nt * 8 + qr;
                bfr[nt][0] = f2tf32(Bs[(kb + qc) * B_STRIDE + nc]);
                bfr[nt][1] = f2tf32(Bs[(kb + qc + 4) * B_STRIDE + nc]);
            }
#pragma unroll
            for (int mt = 0; mt < 2; mt++)
#pragma unroll
                for (int nt = 0; nt < 8; nt++)
                    mma_tf32(acc[mt][nt], afr[mt], bfr[nt]);
        }
        __syncthreads();
    }

#pragma unroll
    for (int mt = 0; mt < 2; mt++) {
        int r0 = m0 + wm0 + mt * 16 + qr;
#pragma unroll
        for (int nt = 0; nt < 8; nt++) {
            int col = n0 + wn0 + nt * 8 + 2 * qc;
            float bx = 0.f, by = 0.f;
            if (useBias) {
                float2 bb = *(const float2*)(bias + col);
                bx = bb.x; by = bb.y;
            }
            float2 v0 = {acc[mt][nt][0] + bx, acc[mt][nt][1] + by};
            float2 v1 = {acc[mt][nt][2] + bx, acc[mt][nt][3] + by};
            *(float2*)(C + (size_t)r0 * GNDIM + col) = v0;
            *(float2*)(C + (size_t)(r0 + 8) * GNDIM + col) = v1;
        }
    }
}

// ---------------------------------------------------------------------------
// Flash attention (causal) with tf32 mma.sync.
// Br=128, Bc=64, 256 threads (8 warps). 2-stage cp.async K/V pipeline.
//   S-phase: warps 4(M) x 2(N), warp tile 32x32, K=Dh=64.
//   softmax: 2 threads per row (32 cols each), online m/l in registers.
//   PV-phase: 8 warps along M, warp tile 16x64, K=Bc=64.
// Strides: Qs/Ks/Ps = 68 (=4 mod 32, conflict-free A/B frag loads),
//          Vs = 72 (=8 mod 32, conflict-free B frag loads).
// ---------------------------------------------------------------------------
struct AttnSmem {
    float Qs[128][68];
    float Ks[2][64][68];
    float Vs[2][64][72];
    float Ps[128][68];
    float red_max[2][128];
    float red_sum[2][128];
    float row_scale[128];
    float row_inv[128];
};

__global__ __launch_bounds__(256)
void attn_mma_kernel(const float* __restrict__ q, const float* __restrict__ k,
                     const float* __restrict__ v, float* __restrict__ out)
{
    extern __shared__ char smem_raw[];
    AttnSmem& sm = *reinterpret_cast<AttnSmem*>(smem_raw);

    const int tid = threadIdx.x;
    const int wid = tid >> 5;
    const int lane = tid & 31;
    const int qr = lane >> 2;        // 0..7
    const int qc = lane & 3;         // 0..3
    const int q0 = blockIdx.x * 128;
    const int bh = blockIdx.y;
    const int b = bh >> 4;
    const int h = bh & 15;

    const size_t base = (size_t)b * SEQ * DMODEL + (size_t)h * HDIM;

    // Load Q tile, pre-scaled by 1/sqrt(Dh)
    for (int idx = tid; idx < 2048; idx += 256) {   // 128 rows x 16 float4
        int r = idx >> 4;
        int d4 = (idx & 15) << 2;
        float4 val = *(const float4*)(q + base + (size_t)(q0 + r) * DMODEL + d4);
        sm.Qs[r][d4 + 0] = val.x * 0.125f;
        sm.Qs[r][d4 + 1] = val.y * 0.125f;
        sm.Qs[r][d4 + 2] = val.z * 0.125f;
        sm.Qs[r][d4 + 3] = val.w * 0.125f;
    }

    // K/V stage loader (cp.async)
    auto load_kv = [&](int st, int k0) {
#pragma unroll
        for (int i = 0; i < 4; i++) {
            int idx = tid + i * 256;          // 0..1023 = 64 rows x 16 chunks
            int c = idx >> 4;
            int d4 = (idx & 15) << 2;
            cp_async16(smem_to_u32(&sm.Ks[st][c][d4]),
                       k + base + (size_t)(k0 + c) * DMODEL + d4);
            cp_async16(smem_to_u32(&sm.Vs[st][c][d4]),
                       v + base + (size_t)(k0 + c) * DMODEL + d4);
        }
    };

    // Softmax ownership: 2 threads per row
    const int srow = tid >> 1;       // 0..127
    const int shalf = tid & 1;       // 0..1
    const int sc0 = shalf * 32;
    float m_i = -INFINITY;
    float l_i = 0.f;

    // PV accumulator: warp wid owns rows [wid*16, wid*16+16)
    float oacc[8][4];
#pragma unroll
    for (int nt = 0; nt < 8; nt++)
#pragma unroll
        for (int l = 0; l < 4; l++) oacc[nt][l] = 0.f;

    // S-phase warp layout
    const int wm = (wid & 3) * 32;
    const int wn = (wid >> 2) * 32;

    const int nkt = (q0 >> 6) + 2;   // number of 64-wide K tiles

    load_kv(0, 0);
    CP_COMMIT();

    for (int kt = 0; kt < nkt; kt++) {
        const int st = kt & 1;
        const int k0 = kt * 64;

        CP_WAIT0();
        __syncthreads();

        if (kt + 1 < nkt) load_kv(st ^ 1, k0 + 64);
        CP_COMMIT();

        // ---- S = Q @ K^T (warp tile 32x32) ----
        float sacc[2][4][4];
#pragma unroll
        for (int mt = 0; mt < 2; mt++)
#pragma unroll
            for (int nt = 0; nt < 4; nt++)
#pragma unroll
                for (int l = 0; l < 4; l++) sacc[mt][nt][l] = 0.f;

#pragma unroll
        for (int ks = 0; ks < 8; ks++) {
            const int kb = ks * 8;
            uint32_t afr[2][4];
            uint32_t bfr[4][2];
#pragma unroll
            for (int mt = 0; mt < 2; mt++) {
                int mbase = wm + mt * 16;
                afr[mt][0] = f2tf32(sm.Qs[mbase + qr][kb + qc]);
                afr[mt][1] = f2tf32(sm.Qs[mbase + qr + 8][kb + qc]);
                afr[mt][2] = f2tf32(sm.Qs[mbase + qr][kb + qc + 4]);
                afr[mt][3] = f2tf32(sm.Qs[mbase + qr + 8][kb + qc + 4]);
            }
#pragma unroll
            for (int nt = 0; nt < 4; nt++) {
                int nc = wn + nt * 8 + qr;
                bfr[nt][0] = f2tf32(sm.Ks[st][nc][kb + qc]);
                bfr[nt][1] = f2tf32(sm.Ks[st][nc][kb + qc + 4]);
            }
#pragma unroll
            for (int mt = 0; mt < 2; mt++)
#pragma unroll
                for (int nt = 0; nt < 4; nt++)
                    mma_tf32(sacc[mt][nt], afr[mt], bfr[nt]);
        }

        // Write S fragments to Ps
#pragma unroll
        for (int mt = 0; mt < 2; mt++) {
            int r0 = wm + mt * 16 + qr;
#pragma unroll
            for (int nt = 0; nt < 4; nt++) {
                int col = wn + nt * 8 + 2 * qc;
                *(float2*)&sm.Ps[r0][col]     = make_float2(sacc[mt][nt][0], sacc[mt][nt][1]);
                *(float2*)&sm.Ps[r0 + 8][col] = make_float2(sacc[mt][nt][2], sacc[mt][nt][3]);
            }
        }
        __syncthreads();

        // ---- Online softmax ----
        {
            const int climit = q0 + srow - k0;        // keep cols c <= climit
            const bool nomask = (climit >= sc0 + 31);
            float mloc = -INFINITY;
            if (nomask) {
#pragma unroll
                for (int c4 = 0; c4 < 8; c4++) {
                    float4 vv = *(const float4*)&sm.Ps[srow][sc0 + c4 * 4];
                    mloc = fmaxf(mloc, fmaxf(fmaxf(vv.x, vv.y), fmaxf(vv.z, vv.w)));
                }
            } else {
#pragma unroll
                for (int c4 = 0; c4 < 8; c4++) {
                    float4 vv = *(const float4*)&sm.Ps[srow][sc0 + c4 * 4];
                    int c = sc0 + c4 * 4;
                    if (c + 0 <= climit) mloc = fmaxf(mloc, vv.x);
                    if (c + 1 <= climit) mloc = fmaxf(mloc, vv.y);
                    if (c + 2 <= climit) mloc = fmaxf(mloc, vv.z);
                    if (c + 3 <= climit) mloc = fmaxf(mloc, vv.w);
                }
            }
            sm.red_max[shalf][srow] = mloc;
            __syncthreads();
            float mtile = fmaxf(sm.red_max[0][srow], sm.red_max[1][srow]);
            float mnew = fmaxf(m_i, mtile);
            float rs = __expf(m_i - mnew);
            if (shalf == 0) sm.row_scale[srow] = rs;

            float lsum = 0.f;
            if (nomask) {
#pragma unroll
                for (int c4 = 0; c4 < 8; c4++) {
                    float4 vv = *(float4*)&sm.Ps[srow][sc0 + c4 * 4];
                    vv.x = __expf(vv.x - mnew);
                    vv.y = __expf(vv.y - mnew);
                    vv.z = __expf(vv.z - mnew);
                    vv.w = __expf(vv.w - mnew);
                    lsum += vv.x + vv.y + vv.z + vv.w;
                    *(float4*)&sm.Ps[srow][sc0 + c4 * 4] = vv;
                }
            } else {
#pragma unroll
                for (int c4 = 0; c4 < 8; c4++) {
                    float4 vv = *(float4*)&sm.Ps[srow][sc0 + c4 * 4];
                    int c = sc0 + c4 * 4;
                    vv.x = (c + 0 <= climit) ? __expf(vv.x - mnew) : 0.f;
                    vv.y = (c + 1 <= climit) ? __expf(vv.y - mnew) : 0.f;
                    vv.z = (c + 2 <= climit) ? __expf(vv.z - mnew) : 0.f;
                    vv.w = (c + 3 <= climit) ? __expf(vv.w - mnew) : 0.f;
                    lsum += vv.x + vv.y + vv.z + vv.w;
                    *(float4*)&sm.Ps[srow][sc0 + c4 * 4] = vv;
                }
            }
            sm.red_sum[shalf][srow] = lsum;
            __syncthreads();
            l_i = l_i * rs + sm.red_sum[0][srow] + sm.red_sum[1][srow];
            m_i = mnew;
        }

        // ---- O = O*rs + P @ V (warp tile 16x64) ----
        {
            const int mbase = wid * 16;
            float rs0 = sm.row_scale[mbase + qr];
            float rs1 = sm.row_scale[mbase + qr + 8];
#pragma unroll
            for (int nt = 0; nt < 8; nt++) {
                oacc[nt][0] *= rs0; oacc[nt][1] *= rs0;
                oacc[nt][2] *= rs1; oacc[nt][3] *= rs1;
            }
#pragma unroll
            for (int ks = 0; ks < 8; ks++) {
                const int kb = ks * 8;
                uint32_t afr[4];
                afr[0] = f2tf32(sm.Ps[mbase + qr][kb + qc]);
                afr[1] = f2tf32(sm.Ps[mbase + qr + 8][kb + qc]);
                afr[2] = f2tf32(sm.Ps[mbase + qr][kb + qc + 4]);
                afr[3] = f2tf32(sm.Ps[mbase + qr + 8][kb + qc + 4]);
                uint32_t bfr[8][2];
#pragma unroll
                for (int nt = 0; nt < 8; nt++) {
                    int nc = nt * 8 + qr;
                    bfr[nt][0] = f2tf32(sm.Vs[st][kb + qc][nc]);
                    bfr[nt][1] = f2tf32(sm.Vs[st][kb + qc + 4][nc]);
                }
#pragma unroll
                for (int nt = 0; nt < 8; nt++)
                    mma_tf32(oacc[nt], afr, bfr[nt]);
            }
        }
        __syncthreads();
    }

    // Final normalization
    if (shalf == 0) sm.row_inv[srow] = 1.f / l_i;
    __syncthreads();

    {
        const int mbase = wid * 16;
        float inv0 = sm.row_inv[mbase + qr];
        float inv1 = sm.row_inv[mbase + qr + 8];
        size_t r0 = base + (size_t)(q0 + mbase + qr) * DMODEL;
        size_t r1 = base + (size_t)(q0 + mbase + qr + 8) * DMODEL;
#pragma unroll
        for (int nt = 0; nt < 8; nt++) {
            int col = nt * 8 + 2 * qc;
            *(float2*)(out + r0 + col) = make_float2(oacc[nt][0] * inv0, oacc[nt][1] * inv0);
            *(float2*)(out + r1 + col) = make_float2(oacc[nt][2] * inv1, oacc[nt][3] * inv1);
        }
    }
}

// ---------------------------------------------------------------------------
// Launch
// ---------------------------------------------------------------------------
extern "C" void kernel_launch(void* const* d_in, const int* in_sizes, int n_in,
                              void* d_out, int out_size)
{
    const float* x  = (const float*)d_in[0];
    const float* Wq = (const float*)d_in[1];
    const float* Wk = (const float*)d_in[2];
    const float* Wv = (const float*)d_in[3];
    const float* Wo = (const float*)d_in[4];
    const float* bo = (const float*)d_in[5];
    float* out = (float*)d_out;

    float *qp, *kp, *vp, *ap;
    cudaGetSymbolAddress((void**)&qp, g_q);
    cudaGetSymbolAddress((void**)&kp, g_k);
    cudaGetSymbolAddress((void**)&vp, g_v);
    cudaGetSymbolAddress((void**)&ap, g_attn);

    cudaFuncSetAttribute(gemm_tc_kernel, cudaFuncAttributeMaxDynamicSharedMemorySize, GEMM_SMEM);
    cudaFuncSetAttribute(attn_mma_kernel, cudaFuncAttributeMaxDynamicSharedMemorySize,
                         (int)sizeof(AttnSmem));

    dim3 ggrid(GNDIM / 128, MTOT / 128);   // (8, 64)

    gemm_tc_kernel<<<ggrid, 256, GEMM_SMEM>>>(x, Wq, nullptr, qp, 0);
    gemm_tc_kernel<<<ggrid, 256, GEMM_SMEM>>>(x, Wk, nullptr, kp, 0);
    gemm_tc_kernel<<<ggrid, 256, GEMM_SMEM>>>(x, Wv, nullptr, vp, 0);

    dim3 agrid(SEQ / 128, BATCH * NHEADS);  // (16, 64)
    attn_mma_kernel<<<agrid, 256, sizeof(AttnSmem)>>>(qp, kp, vp, ap);

    gemm_tc_kernel<<<ggrid, 256, GEMM_SMEM>>>(ap, Wo, bo, out, 1);
}

// round 6
// speedup vs baseline: 2.7774x; 1.0674x over previous
#include <cuda_runtime.h>
#include <cuda_bf16.h>
#include <math.h>
#include <stdint.h>

// Problem constants
#define BATCH 4
#define SEQ 2048
#define DMODEL 1024
#define NHEADS 16
#define HDIM 64
#define MTOT (BATCH * SEQ)          // 8192 rows

// ---------------------------------------------------------------------------
// Scratch (device globals: allocation-free, graph-safe)
// ---------------------------------------------------------------------------
__device__ float g_q[MTOT * DMODEL];
__device__ float g_k[MTOT * DMODEL];
__device__ float g_v[MTOT * DMODEL];
__device__ float g_attn[MTOT * DMODEL];

// ---------------------------------------------------------------------------
// Helpers
// ---------------------------------------------------------------------------
__device__ __forceinline__ uint32_t smem_to_u32(const void* p) {
    uint32_t a;
    asm("{ .reg .u64 t; cvta.to.shared.u64 t, %1; cvt.u32.u64 %0, t; }"
        : "=r"(a) : "l"(p));
    return a;
}
__device__ __forceinline__ void cp_async16(uint32_t dst, const void* src) {
    asm volatile("cp.async.cg.shared.global [%0], [%1], 16;" :: "r"(dst), "l"(src));
}
#define CP_COMMIT() asm volatile("cp.async.commit_group;" ::: "memory")
#define CP_WAIT0()  asm volatile("cp.async.wait_group 0;" ::: "memory")
#define CP_WAIT2()  asm volatile("cp.async.wait_group 2;" ::: "memory")

__device__ __forceinline__ uint32_t f2tf32(float f) {
    uint32_t r;
    asm("cvt.rna.tf32.f32 %0, %1;" : "=r"(r) : "f"(f));
    return r;
}
__device__ __forceinline__ void mma_tf32(float* c, const uint32_t* a, const uint32_t* b) {
    asm volatile(
        "mma.sync.aligned.m16n8k8.row.col.f32.tf32.tf32.f32 "
        "{%0,%1,%2,%3}, {%4,%5,%6,%7}, {%8,%9}, {%0,%1,%2,%3};"
        : "+f"(c[0]), "+f"(c[1]), "+f"(c[2]), "+f"(c[3])
        : "r"(a[0]), "r"(a[1]), "r"(a[2]), "r"(a[3]), "r"(b[0]), "r"(b[1]));
}

// ---------------------------------------------------------------------------
// tf32 mma.sync GEMM core (BM=128 BN=128 BK=16, 256 thr, 3-stage cp.async).
// Templated over output selection so QKV fuses into one launch.
// ---------------------------------------------------------------------------
#define GKDIM 1024
#define GNDIM 1024
#define NKT 64
#define A_STRIDE 20
#define B_STRIDE 136
#define A_BYTES (128 * A_STRIDE * 4)
#define B_BYTES (16 * B_STRIDE * 4)
#define STAGE_BYTES (A_BYTES + B_BYTES)
#define GSTAGES 3
#define GEMM_SMEM (GSTAGES * STAGE_BYTES)

__device__ __forceinline__ void gemm_core(const float* __restrict__ A,
                                          const float* __restrict__ B,
                                          const float* __restrict__ bias,
                                          float* __restrict__ C,
                                          int m0, int n0, int useBias,
                                          char* dsmem)
{
    const int tid = threadIdx.x;
    const int wid = tid >> 5;
    const int lane = tid & 31;
    const int wm0 = (wid & 3) * 32;
    const int wn0 = (wid >> 2) * 64;
    const int qr = lane >> 2;
    const int qc = lane & 3;

    const uint32_t sbase = smem_to_u32(dsmem);

    float acc[2][8][4];
#pragma unroll
    for (int i = 0; i < 2; i++)
#pragma unroll
        for (int j = 0; j < 8; j++)
#pragma unroll
            for (int l = 0; l < 4; l++) acc[i][j][l] = 0.f;

    auto issue_stage = [&](int stage, int k0) {
        uint32_t aB = sbase + stage * STAGE_BYTES;
        uint32_t bB = aB + A_BYTES;
#pragma unroll
        for (int i = 0; i < 2; i++) {
            int idx = tid * 2 + i;
            int row = idx >> 2;
            int c4 = idx & 3;
            cp_async16(aB + row * (A_STRIDE * 4) + c4 * 16,
                       A + (size_t)(m0 + row) * GKDIM + k0 + c4 * 4);
            int krow = idx >> 5;
            int col = idx & 31;
            cp_async16(bB + krow * (B_STRIDE * 4) + col * 16,
                       B + (size_t)(k0 + krow) * GNDIM + n0 + col * 4);
        }
    };

    issue_stage(0, 0);
    CP_COMMIT();
    issue_stage(1, 16);
    CP_COMMIT();

    for (int kt = 0; kt < NKT; kt++) {
        int lt = kt + 2;
        if (lt < NKT) issue_stage(lt % GSTAGES, lt * 16);
        CP_COMMIT();
        CP_WAIT2();
        __syncthreads();

        const float* As = (const float*)(dsmem + (kt % GSTAGES) * STAGE_BYTES);
        const float* Bs = (const float*)(dsmem + (kt % GSTAGES) * STAGE_BYTES + A_BYTES);

#pragma unroll
        for (int ks = 0; ks < 2; ks++) {
            const int kb = ks * 8;
            uint32_t afr[2][4];
            uint32_t bfr[8][2];
#pragma unroll
            for (int mt = 0; mt < 2; mt++) {
                int mbase = wm0 + mt * 16;
                afr[mt][0] = f2tf32(As[(mbase + qr) * A_STRIDE + kb + qc]);
                afr[mt][1] = f2tf32(As[(mbase + qr + 8) * A_STRIDE + kb + qc]);
                afr[mt][2] = f2tf32(As[(mbase + qr) * A_STRIDE + kb + qc + 4]);
                afr[mt][3] = f2tf32(As[(mbase + qr + 8) * A_STRIDE + kb + qc + 4]);
            }
#pragma unroll
            for (int nt = 0; nt < 8; nt++) {
                int nc = wn0 + nt * 8 + qr;
                bfr[nt][0] = f2tf32(Bs[(kb + qc) * B_STRIDE + nc]);
                bfr[nt][1] = f2tf32(Bs[(kb + qc + 4) * B_STRIDE + nc]);
            }
#pragma unroll
            for (int mt = 0; mt < 2; mt++)
#pragma unroll
                for (int nt = 0; nt < 8; nt++)
                    mma_tf32(acc[mt][nt], afr[mt], bfr[nt]);
        }
        __syncthreads();
    }

#pragma unroll
    for (int mt = 0; mt < 2; mt++) {
        int r0 = m0 + wm0 + mt * 16 + qr;
#pragma unroll
        for (int nt = 0; nt < 8; nt++) {
            int col = n0 + wn0 + nt * 8 + 2 * qc;
            float bx = 0.f, by = 0.f;
            if (useBias) {
                float2 bb = *(const float2*)(bias + col);
                bx = bb.x; by = bb.y;
            }
            float2 v0 = {acc[mt][nt][0] + bx, acc[mt][nt][1] + by};
            float2 v1 = {acc[mt][nt][2] + bx, acc[mt][nt][3] + by};
            *(float2*)(C + (size_t)r0 * GNDIM + col) = v0;
            *(float2*)(C + (size_t)(r0 + 8) * GNDIM + col) = v1;
        }
    }
}

// Fused QKV: grid.x = 24 (3 weights x 8 N-tiles), grid.y = 64 (M-tiles)
__global__ __launch_bounds__(256)
void gemm_qkv_kernel(const float* __restrict__ x,
                     const float* __restrict__ Wq, const float* __restrict__ Wk,
                     const float* __restrict__ Wv,
                     float* __restrict__ q, float* __restrict__ k,
                     float* __restrict__ v)
{
    extern __shared__ char dsmem[];
    const int sel = blockIdx.x >> 3;
    const int n0 = (blockIdx.x & 7) * 128;
    const int m0 = blockIdx.y * 128;
    const float* B = (sel == 0) ? Wq : (sel == 1) ? Wk : Wv;
    float* C = (sel == 0) ? q : (sel == 1) ? k : v;
    gemm_core(x, B, nullptr, C, m0, n0, 0, dsmem);
}

__global__ __launch_bounds__(256)
void gemm_tc_kernel(const float* __restrict__ A, const float* __restrict__ B,
                    const float* __restrict__ bias, float* __restrict__ C,
                    int useBias)
{
    extern __shared__ char dsmem[];
    gemm_core(A, B, bias, C, blockIdx.y * 128, blockIdx.x * 128, useBias, dsmem);
}

// ---------------------------------------------------------------------------
// Flash attention (causal) with tf32 mma.sync.
// Br=128, Bc=64, 256 threads (8 warps). SINGLE-buffered K/V (fits 2 CTA/SM);
// K(kt+1) prefetched during softmax/PV. Heaviest Q-tiles launch first.
// ---------------------------------------------------------------------------
struct AttnSmem {
    float Qs[128][68];
    float Ks[64][68];
    float Vs[64][72];
    float Ps[128][68];
    float red_max[2][128];
    float red_sum[2][128];
    float row_scale[128];
    float row_inv[128];
};   // ~106 KB

__global__ __launch_bounds__(256, 2)
void attn_mma_kernel(const float* __restrict__ q, const float* __restrict__ k,
                     const float* __restrict__ v, float* __restrict__ out)
{
    extern __shared__ char smem_raw[];
    AttnSmem& sm = *reinterpret_cast<AttnSmem*>(smem_raw);

    const int tid = threadIdx.x;
    const int wid = tid >> 5;
    const int lane = tid & 31;
    const int qr = lane >> 2;        // 0..7
    const int qc = lane & 3;         // 0..3
    const int q0 = (gridDim.x - 1 - blockIdx.x) * 128;   // heavy tiles first
    const int bh = blockIdx.y;
    const int b = bh >> 4;
    const int h = bh & 15;

    const size_t base = (size_t)b * SEQ * DMODEL + (size_t)h * HDIM;

    // Load Q tile, pre-scaled by 1/sqrt(Dh)
    for (int idx = tid; idx < 2048; idx += 256) {   // 128 rows x 16 float4
        int r = idx >> 4;
        int d4 = (idx & 15) << 2;
        float4 val = *(const float4*)(q + base + (size_t)(q0 + r) * DMODEL + d4);
        sm.Qs[r][d4 + 0] = val.x * 0.125f;
        sm.Qs[r][d4 + 1] = val.y * 0.125f;
        sm.Qs[r][d4 + 2] = val.z * 0.125f;
        sm.Qs[r][d4 + 3] = val.w * 0.125f;
    }

    auto load_k = [&](int k0) {
#pragma unroll
        for (int i = 0; i < 4; i++) {
            int idx = tid + i * 256;
            int c = idx >> 4;
            int d4 = (idx & 15) << 2;
            cp_async16(smem_to_u32(&sm.Ks[c][d4]),
                       k + base + (size_t)(k0 + c) * DMODEL + d4);
        }
    };
    auto load_v = [&](int k0) {
#pragma unroll
        for (int i = 0; i < 4; i++) {
            int idx = tid + i * 256;
            int c = idx >> 4;
            int d4 = (idx & 15) << 2;
            cp_async16(smem_to_u32(&sm.Vs[c][d4]),
                       v + base + (size_t)(k0 + c) * DMODEL + d4);
        }
    };

    // Softmax ownership: 2 threads per row
    const int srow = tid >> 1;       // 0..127
    const int shalf = tid & 1;       // 0..1
    const int sc0 = shalf * 32;
    float m_i = -INFINITY;
    float l_i = 0.f;

    float oacc[8][4];
#pragma unroll
    for (int nt = 0; nt < 8; nt++)
#pragma unroll
        for (int l = 0; l < 4; l++) oacc[nt][l] = 0.f;

    const int wm = (wid & 3) * 32;
    const int wn = (wid >> 2) * 32;

    const int nkt = (q0 >> 6) + 2;

    load_k(0);
    CP_COMMIT();

    for (int kt = 0; kt < nkt; kt++) {
        const int k0 = kt * 64;

        load_v(k0);
        CP_COMMIT();
        CP_WAIT0();               // K(kt) + V(kt) resident
        __syncthreads();

        // ---- S = Q @ K^T (warp tile 32x32) ----
        float sacc[2][4][4];
#pragma unroll
        for (int mt = 0; mt < 2; mt++)
#pragma unroll
            for (int nt = 0; nt < 4; nt++)
#pragma unroll
                for (int l = 0; l < 4; l++) sacc[mt][nt][l] = 0.f;

#pragma unroll
        for (int ks = 0; ks < 8; ks++) {
            const int kb = ks * 8;
            uint32_t afr[2][4];
            uint32_t bfr[4][2];
#pragma unroll
            for (int mt = 0; mt < 2; mt++) {
                int mbase = wm + mt * 16;
                afr[mt][0] = f2tf32(sm.Qs[mbase + qr][kb + qc]);
                afr[mt][1] = f2tf32(sm.Qs[mbase + qr + 8][kb + qc]);
                afr[mt][2] = f2tf32(sm.Qs[mbase + qr][kb + qc + 4]);
                afr[mt][3] = f2tf32(sm.Qs[mbase + qr + 8][kb + qc + 4]);
            }
#pragma unroll
            for (int nt = 0; nt < 4; nt++) {
                int nc = wn + nt * 8 + qr;
                bfr[nt][0] = f2tf32(sm.Ks[nc][kb + qc]);
                bfr[nt][1] = f2tf32(sm.Ks[nc][kb + qc + 4]);
            }
#pragma unroll
            for (int mt = 0; mt < 2; mt++)
#pragma unroll
                for (int nt = 0; nt < 4; nt++)
                    mma_tf32(sacc[mt][nt], afr[mt], bfr[nt]);
        }

        // Write S fragments to Ps
#pragma unroll
        for (int mt = 0; mt < 2; mt++) {
            int r0 = wm + mt * 16 + qr;
#pragma unroll
            for (int nt = 0; nt < 4; nt++) {
                int col = wn + nt * 8 + 2 * qc;
                *(float2*)&sm.Ps[r0][col]     = make_float2(sacc[mt][nt][0], sacc[mt][nt][1]);
                *(float2*)&sm.Ps[r0 + 8][col] = make_float2(sacc[mt][nt][2], sacc[mt][nt][3]);
            }
        }
        __syncthreads();          // Ps complete; all warps done reading Ks

        // Prefetch K(kt+1) — overlaps softmax + PV
        if (kt + 1 < nkt) {
            load_k(k0 + 64);
            CP_COMMIT();
        }

        // ---- Online softmax ----
        {
            const int climit = q0 + srow - k0;
            const bool nomask = (climit >= sc0 + 31);
            float mloc = -INFINITY;
            if (nomask) {
#pragma unroll
                for (int c4 = 0; c4 < 8; c4++) {
                    float4 vv = *(const float4*)&sm.Ps[srow][sc0 + c4 * 4];
                    mloc = fmaxf(mloc, fmaxf(fmaxf(vv.x, vv.y), fmaxf(vv.z, vv.w)));
                }
            } else {
#pragma unroll
                for (int c4 = 0; c4 < 8; c4++) {
                    float4 vv = *(const float4*)&sm.Ps[srow][sc0 + c4 * 4];
                    int c = sc0 + c4 * 4;
                    if (c + 0 <= climit) mloc = fmaxf(mloc, vv.x);
                    if (c + 1 <= climit) mloc = fmaxf(mloc, vv.y);
                    if (c + 2 <= climit) mloc = fmaxf(mloc, vv.z);
                    if (c + 3 <= climit) mloc = fmaxf(mloc, vv.w);
                }
            }
            sm.red_max[shalf][srow] = mloc;
            __syncthreads();
            float mtile = fmaxf(sm.red_max[0][srow], sm.red_max[1][srow]);
            float mnew = fmaxf(m_i, mtile);
            float rs = __expf(m_i - mnew);
            if (shalf == 0) sm.row_scale[srow] = rs;

            float lsum = 0.f;
            if (nomask) {
#pragma unroll
                for (int c4 = 0; c4 < 8; c4++) {
                    float4 vv = *(float4*)&sm.Ps[srow][sc0 + c4 * 4];
                    vv.x = __expf(vv.x - mnew);
                    vv.y = __expf(vv.y - mnew);
                    vv.z = __expf(vv.z - mnew);
                    vv.w = __expf(vv.w - mnew);
                    lsum += vv.x + vv.y + vv.z + vv.w;
                    *(float4*)&sm.Ps[srow][sc0 + c4 * 4] = vv;
                }
            } else {
#pragma unroll
                for (int c4 = 0; c4 < 8; c4++) {
                    float4 vv = *(float4*)&sm.Ps[srow][sc0 + c4 * 4];
                    int c = sc0 + c4 * 4;
                    vv.x = (c + 0 <= climit) ? __expf(vv.x - mnew) : 0.f;
                    vv.y = (c + 1 <= climit) ? __expf(vv.y - mnew) : 0.f;
                    vv.z = (c + 2 <= climit) ? __expf(vv.z - mnew) : 0.f;
                    vv.w = (c + 3 <= climit) ? __expf(vv.w - mnew) : 0.f;
                    lsum += vv.x + vv.y + vv.z + vv.w;
                    *(float4*)&sm.Ps[srow][sc0 + c4 * 4] = vv;
                }
            }
            sm.red_sum[shalf][srow] = lsum;
            __syncthreads();
            l_i = l_i * rs + sm.red_sum[0][srow] + sm.red_sum[1][srow];
            m_i = mnew;
        }

        // ---- O = O*rs + P @ V (warp tile 16x64) ----
        {
            const int mbase = wid * 16;
            float rs0 = sm.row_scale[mbase + qr];
            float rs1 = sm.row_scale[mbase + qr + 8];
#pragma unroll
            for (int nt = 0; nt < 8; nt++) {
                oacc[nt][0] *= rs0; oacc[nt][1] *= rs0;
                oacc[nt][2] *= rs1; oacc[nt][3] *= rs1;
            }
#pragma unroll
            for (int ks = 0; ks < 8; ks++) {
                const int kb = ks * 8;
                uint32_t afr[4];
                afr[0] = f2tf32(sm.Ps[mbase + qr][kb + qc]);
                afr[1] = f2tf32(sm.Ps[mbase + qr + 8][kb + qc]);
                afr[2] = f2tf32(sm.Ps[mbase + qr][kb + qc + 4]);
                afr[3] = f2tf32(sm.Ps[mbase + qr + 8][kb + qc + 4]);
                uint32_t bfr[8][2];
#pragma unroll
                for (int nt = 0; nt < 8; nt++) {
                    int nc = nt * 8 + qr;
                    bfr[nt][0] = f2tf32(sm.Vs[kb + qc][nc]);
                    bfr[nt][1] = f2tf32(sm.Vs[kb + qc + 4][nc]);
                }
#pragma unroll
                for (int nt = 0; nt < 8; nt++)
                    mma_tf32(oacc[nt], afr, bfr[nt]);
            }
        }
        __syncthreads();          // all done with Vs/Ps before next overwrite
    }

    // Final normalization
    if (shalf == 0) sm.row_inv[srow] = 1.f / l_i;
    __syncthreads();

    {
        const int mbase = wid * 16;
        float inv0 = sm.row_inv[mbase + qr];
        float inv1 = sm.row_inv[mbase + qr + 8];
        size_t r0 = base + (size_t)(q0 + mbase + qr) * DMODEL;
        size_t r1 = base + (size_t)(q0 + mbase + qr + 8) * DMODEL;
#pragma unroll
        for (int nt = 0; nt < 8; nt++) {
            int col = nt * 8 + 2 * qc;
            *(float2*)(out + r0 + col) = make_float2(oacc[nt][0] * inv0, oacc[nt][1] * inv0);
            *(float2*)(out + r1 + col) = make_float2(oacc[nt][2] * inv1, oacc[nt][3] * inv1);
        }
    }
}

// ---------------------------------------------------------------------------
// Launch
// ---------------------------------------------------------------------------
extern "C" void kernel_launch(void* const* d_in, const int* in_sizes, int n_in,
                              void* d_out, int out_size)
{
    const float* x  = (const float*)d_in[0];
    const float* Wq = (const float*)d_in[1];
    const float* Wk = (const float*)d_in[2];
    const float* Wv = (const float*)d_in[3];
    const float* Wo = (const float*)d_in[4];
    const float* bo = (const float*)d_in[5];
    float* out = (float*)d_out;

    float *qp, *kp, *vp, *ap;
    cudaGetSymbolAddress((void**)&qp, g_q);
    cudaGetSymbolAddress((void**)&kp, g_k);
    cudaGetSymbolAddress((void**)&vp, g_v);
    cudaGetSymbolAddress((void**)&ap, g_attn);

    cudaFuncSetAttribute(gemm_qkv_kernel, cudaFuncAttributeMaxDynamicSharedMemorySize, GEMM_SMEM);
    cudaFuncSetAttribute(gemm_tc_kernel, cudaFuncAttributeMaxDynamicSharedMemorySize, GEMM_SMEM);
    cudaFuncSetAttribute(attn_mma_kernel, cudaFuncAttributeMaxDynamicSharedMemorySize,
                         (int)sizeof(AttnSmem));

    // Fused QKV projections
    dim3 qkvgrid(24, MTOT / 128);   // (24, 64)
    gemm_qkv_kernel<<<qkvgrid, 256, GEMM_SMEM>>>(x, Wq, Wk, Wv, qp, kp, vp);

    // Causal flash attention
    dim3 agrid(SEQ / 128, BATCH * NHEADS);  // (16, 64)
    attn_mma_kernel<<<agrid, 256, sizeof(AttnSmem)>>>(qp, kp, vp, ap);

    // Output projection + bias
    dim3 ggrid(GNDIM / 128, MTOT / 128);    // (8, 64)
    gemm_tc_kernel<<<ggrid, 256, GEMM_SMEM>>>(ap, Wo, bo, out, 1);
}